// round 7
// baseline (speedup 1.0000x reference)
#include <cuda_runtime.h>
#include <cstdint>

#define N_NODES  100000
#define N_EDGES  6400000
#define IN_DIM   10
#define HIDDEN   16
// Accumulator row stride padded to 12 floats (48B): [sum0..sum9, count, pad]
#define SUM_STRIDE 12
#define SUM_ELEMS  (N_NODES * SUM_STRIDE)

// Scratch: device globals (no allocation allowed). 4.8 MB — L2-resident.
__device__ __align__(16) float g_sum[SUM_ELEMS];
__device__ int g_is64;   // 1 if edge_index is int64, 0 if int32

// ---------------------------------------------------------------------------
// Kernel 0: detect edge_index dtype. Positive int64 little-endian => every
// odd 32-bit word (high half) is zero. Random int32 indices => essentially
// impossible for 256 consecutive odd words to all be zero.
// ---------------------------------------------------------------------------
__global__ void detect_kernel(const int* __restrict__ ei32) {
    if (blockIdx.x == 0 && threadIdx.x == 0) {
        int nz = 0;
        #pragma unroll 8
        for (int i = 0; i < 256; i++) nz |= ei32[2 * i + 1];
        g_is64 = (nz == 0) ? 1 : 0;
    }
}

// ---------------------------------------------------------------------------
// Kernel 1: zero the accumulator (runs every replay — graph-capturable)
// ---------------------------------------------------------------------------
__global__ void zero_kernel() {
    int i = blockIdx.x * blockDim.x + threadIdx.x;
    float4* p = reinterpret_cast<float4*>(g_sum);
    const int n4 = SUM_ELEMS / 4;   // 300,000 float4 stores
    for (int k = i; k < n4; k += gridDim.x * blockDim.x) {
        p[k] = make_float4(0.f, 0.f, 0.f, 0.f);
    }
}

// ---------------------------------------------------------------------------
// Kernel 2: edge scatter. Four edges per thread.
//   Per edge: 3x red.global.add.v4.f32 (degree count folded into lane 10).
// ---------------------------------------------------------------------------
__device__ __forceinline__ void red_add_v4(float* gptr, float a, float b, float c, float d) {
    asm volatile("red.global.add.v4.f32 [%0], {%1, %2, %3, %4};"
                 :: "l"(gptr), "f"(a), "f"(b), "f"(c), "f"(d)
                 : "memory");
}

__device__ __forceinline__ void scatter_one(const float* __restrict__ x, int src, int dst) {
    // x row: 10 floats, 40B stride -> 8B aligned -> five float2 loads (L2-hit gathers)
    const float2* xr = reinterpret_cast<const float2*>(x + (size_t)src * IN_DIM);
    float2 a0 = __ldg(xr + 0);
    float2 a1 = __ldg(xr + 1);
    float2 a2 = __ldg(xr + 2);
    float2 a3 = __ldg(xr + 3);
    float2 a4 = __ldg(xr + 4);

    float* s = g_sum + (size_t)dst * SUM_STRIDE;   // 48B-aligned row
    red_add_v4(s + 0, a0.x, a0.y, a1.x, a1.y);
    red_add_v4(s + 4, a2.x, a2.y, a3.x, a3.y);
    red_add_v4(s + 8, a4.x, a4.y, 1.0f, 0.0f);     // count folded in
}

__global__ void __launch_bounds__(256) edge_kernel(
    const void*  __restrict__ eiv,   // [2, N_EDGES] int32 OR int64
    const float* __restrict__ x)     // [N_NODES, IN_DIM]
{
    int t = blockIdx.x * blockDim.x + threadIdx.x;
    int e0 = t * 4;
    if (e0 >= N_EDGES) return;

    int s[4], d[4];
    if (g_is64 == 0) {
        // int32 path: one 16B vector load per stream covers 4 edges.
        const int4* sbase = reinterpret_cast<const int4*>(eiv);
        int4 sv = __ldcs(sbase + t);
        int4 dv = __ldcs(sbase + (N_EDGES / 4) + t);
        s[0] = sv.x; s[1] = sv.y; s[2] = sv.z; s[3] = sv.w;
        d[0] = dv.x; d[1] = dv.y; d[2] = dv.z; d[3] = dv.w;
    } else {
        // int64 path: two 16B vector loads per stream.
        const longlong2* b = reinterpret_cast<const longlong2*>(eiv);
        longlong2 s0 = __ldcs(b + t * 2);
        longlong2 s1 = __ldcs(b + t * 2 + 1);
        longlong2 d0 = __ldcs(b + (N_EDGES / 2) + t * 2);
        longlong2 d1 = __ldcs(b + (N_EDGES / 2) + t * 2 + 1);
        s[0] = (int)s0.x; s[1] = (int)s0.y; s[2] = (int)s1.x; s[3] = (int)s1.y;
        d[0] = (int)d0.x; d[1] = (int)d0.y; d[2] = (int)d1.x; d[3] = (int)d1.y;
    }

    #pragma unroll
    for (int k = 0; k < 4; k++) scatter_one(x, s[k], d[k]);
}

// ---------------------------------------------------------------------------
// Kernel 3: per-node epilogue. out = (sum/max(cnt,1)) @ W_l + b + x @ W_r
// ---------------------------------------------------------------------------
__global__ void __launch_bounds__(256) node_kernel(
    const float* __restrict__ x,      // [N, 10]
    const float* __restrict__ W_l,    // [10, 16]
    const float* __restrict__ b_l,    // [16]
    const float* __restrict__ W_r,    // [10, 16]
    float*       __restrict__ out)    // [N, 16]
{
    __shared__ float sWl[IN_DIM * HIDDEN];
    __shared__ float sWr[IN_DIM * HIDDEN];
    __shared__ float sB[HIDDEN];

    for (int k = threadIdx.x; k < IN_DIM * HIDDEN; k += blockDim.x) {
        sWl[k] = W_l[k];
        sWr[k] = W_r[k];
    }
    if (threadIdx.x < HIDDEN) sB[threadIdx.x] = b_l[threadIdx.x];
    __syncthreads();

    int n = blockIdx.x * blockDim.x + threadIdx.x;
    if (n >= N_NODES) return;

    // Accumulator row: 12 floats, 48B-aligned -> three float4
    const float4* sp = reinterpret_cast<const float4*>(g_sum + (size_t)n * SUM_STRIDE);
    float4 s0 = sp[0], s1 = sp[1], s2 = sp[2];
    float sums[IN_DIM] = {s0.x, s0.y, s0.z, s0.w, s1.x, s1.y, s1.z, s1.w, s2.x, s2.y};
    float cnt = s2.z;
    float inv = 1.0f / fmaxf(cnt, 1.0f);

    // x row: five float2
    const float2* xr = reinterpret_cast<const float2*>(x + (size_t)n * IN_DIM);
    float xv[IN_DIM];
    #pragma unroll
    for (int i = 0; i < 5; i++) {
        float2 v = __ldg(xr + i);
        xv[2 * i]     = v.x;
        xv[2 * i + 1] = v.y;
    }

    float m[IN_DIM];
    #pragma unroll
    for (int d = 0; d < IN_DIM; d++) m[d] = sums[d] * inv;

    float acc[HIDDEN];
    #pragma unroll
    for (int h = 0; h < HIDDEN; h++) acc[h] = sB[h];

    #pragma unroll
    for (int d = 0; d < IN_DIM; d++) {
        float md = m[d], xd = xv[d];
        #pragma unroll
        for (int h = 0; h < HIDDEN; h++) {
            acc[h] = fmaf(md, sWl[d * HIDDEN + h], acc[h]);
            acc[h] = fmaf(xd, sWr[d * HIDDEN + h], acc[h]);
        }
    }

    float4* op = reinterpret_cast<float4*>(out + (size_t)n * HIDDEN);
    op[0] = make_float4(acc[0],  acc[1],  acc[2],  acc[3]);
    op[1] = make_float4(acc[4],  acc[5],  acc[6],  acc[7]);
    op[2] = make_float4(acc[8],  acc[9],  acc[10], acc[11]);
    op[3] = make_float4(acc[12], acc[13], acc[14], acc[15]);
}

// ---------------------------------------------------------------------------
extern "C" void kernel_launch(void* const* d_in, const int* in_sizes, int n_in,
                              void* d_out, int out_size) {
    // Size-based input identification (robust to ordering):
    //   x: 1,000,000   edge_index: 12,800,000   W_l/W_r: 160 (in order)   b_l: 16
    const float* x  = nullptr;
    const void*  ei = nullptr;
    const float* Wl = nullptr;
    const float* Wr = nullptr;
    const float* bl = nullptr;
    for (int i = 0; i < n_in; i++) {
        int s = in_sizes[i];
        if      (s == N_NODES * IN_DIM)  x  = (const float*)d_in[i];
        else if (s == 2 * N_EDGES)       ei = d_in[i];
        else if (s == IN_DIM * HIDDEN) { if (!Wl) Wl = (const float*)d_in[i];
                                         else     Wr = (const float*)d_in[i]; }
        else if (s == HIDDEN)            bl = (const float*)d_in[i];
    }
    float* out = (float*)d_out;

    detect_kernel<<<1, 32>>>((const int*)ei);
    zero_kernel<<<592, 256>>>();   // 148 SMs * 4 blocks
    edge_kernel<<<(N_EDGES / 4 + 255) / 256, 256>>>(ei, x);
    node_kernel<<<(N_NODES + 255) / 256, 256>>>(x, Wl, bl, Wr, out);
}